// round 3
// baseline (speedup 1.0000x reference)
#include <cuda_runtime.h>
#include <math.h>

// Problem constants
#define ROWS   49152      // B*T*N = 8*12*512
#define DCH    128        // D
#define NNODES 512        // N
#define NBT    96         // B*T
#define NH     4          // heads (d)
#define MBLK   384        // ROWS / 128

// ---------------- scratch (device globals; no cudaMalloc allowed) ----------
__device__ float g_qraw[ROWS * DCH];
__device__ float g_kraw[ROWS * DCH];
__device__ float g_vraw[ROWS * DCH];
__device__ float g_aout[ROWS * DCH];
__device__ float g_oraw[ROWS * DCH];
__device__ int   g_nbr[NNODES * NNODES];
__device__ int   g_cnt[NNODES];
// deterministic BN partials: [z in 0..3][block 0..383][ch 0..127]
__device__ float g_psum[4 * MBLK * DCH];
__device__ float g_psumsq[4 * MBLK * DCH];
__device__ float g_scale[4 * DCH];
__device__ float g_shift[4 * DCH];

// ---------------- CSR build of adjacency (warp per row, ballot compaction) --
__global__ void build_csr_kernel(const float* __restrict__ A)
{
    int warp = (blockIdx.x * blockDim.x + threadIdx.x) >> 5;
    int lane = threadIdx.x & 31;
    if (warp >= NNODES) return;
    int base = 0;
    for (int m0 = 0; m0 < NNODES; m0 += 32) {
        float a = A[warp * NNODES + m0 + lane];
        unsigned bal = __ballot_sync(0xffffffffu, a > 0.f);
        if (a > 0.f) {
            int pre = __popc(bal & ((1u << lane) - 1u));
            g_nbr[warp * NNODES + base + pre] = m0 + lane;
        }
        base += __popc(bal);
    }
    if (lane == 0) g_cnt[warp] = base;
}

// ---------------- 128x128 tile SGEMM, BK=16, 8x8 per thread -----------------
// CAT=true: A row = [X_row(128) | STE_row(128)], KDIM=256.
// blockIdx.z selects (W,b,Y) among the up-to-3 passed sets.
template <int KDIM, bool CAT>
__global__ __launch_bounds__(256)
void gemm_kernel(const float* __restrict__ A0, const float* __restrict__ A1,
                 const float* __restrict__ W0, const float* __restrict__ W1,
                 const float* __restrict__ W2,
                 const float* __restrict__ b0, const float* __restrict__ b1,
                 const float* __restrict__ b2,
                 float* __restrict__ Y0, float* __restrict__ Y1,
                 float* __restrict__ Y2)
{
    __shared__ __align__(16) float As[16][128];
    __shared__ __align__(16) float Bs[16][128];

    const int z = blockIdx.z;
    const float* W    = (z == 0) ? W0 : (z == 1) ? W1 : W2;
    const float* bias = (z == 0) ? b0 : (z == 1) ? b1 : b2;
    float*       Y    = (z == 0) ? Y0 : (z == 1) ? Y1 : Y2;

    const int tid  = threadIdx.x;
    const int row0 = blockIdx.x * 128;
    const int tr   = tid >> 4;   // 0..15
    const int tc   = tid & 15;   // 0..15

    float acc[8][8];
#pragma unroll
    for (int i = 0; i < 8; i++)
#pragma unroll
        for (int j = 0; j < 8; j++) acc[i][j] = 0.f;

    for (int k0 = 0; k0 < KDIM; k0 += 16) {
        // A tile: 128 rows x 16 k = 512 float4, 2 per thread (store transposed)
#pragma unroll
        for (int t = 0; t < 2; t++) {
            int i4 = tid + 256 * t;          // 0..511
            int m  = i4 >> 2;                // 0..127
            int kq = (i4 & 3) << 2;          // 0,4,8,12
            int gk = k0 + kq;
            const float* src;
            if (CAT) {
                src = (gk < 128)
                    ? (A0 + (size_t)(row0 + m) * 128 + gk)
                    : (A1 + (size_t)(row0 + m) * 128 + (gk - 128));
            } else {
                src = A0 + (size_t)(row0 + m) * KDIM + gk;
            }
            float4 av = *(const float4*)src;
            As[kq + 0][m] = av.x;
            As[kq + 1][m] = av.y;
            As[kq + 2][m] = av.z;
            As[kq + 3][m] = av.w;
        }
        // B tile: 16 x 128 = 512 float4
#pragma unroll
        for (int t = 0; t < 2; t++) {
            int i4 = tid + 256 * t;
            int k  = i4 >> 5;                // 0..15
            int n4 = (i4 & 31) << 2;
            *(float4*)&Bs[k][n4] = *(const float4*)(W + (size_t)(k0 + k) * 128 + n4);
        }
        __syncthreads();

#pragma unroll
        for (int k = 0; k < 16; k++) {
            float ra[8], rb[8];
            *(float4*)&ra[0] = *(const float4*)&As[k][tr * 8];
            *(float4*)&ra[4] = *(const float4*)&As[k][tr * 8 + 4];
            *(float4*)&rb[0] = *(const float4*)&Bs[k][tc * 8];
            *(float4*)&rb[4] = *(const float4*)&Bs[k][tc * 8 + 4];
#pragma unroll
            for (int i = 0; i < 8; i++)
#pragma unroll
                for (int j = 0; j < 8; j++)
                    acc[i][j] = fmaf(ra[i], rb[j], acc[i][j]);
        }
        __syncthreads();
    }

    // epilogue: + bias, store raw (BN applied later)
#pragma unroll
    for (int i = 0; i < 8; i++) {
        size_t row = (size_t)(row0 + tr * 8 + i);
#pragma unroll
        for (int j = 0; j < 8; j++) {
            int col = tc * 8 + j;
            Y[row * 128 + col] = acc[i][j] + bias[col];
        }
    }
}

// ---------------- BN batch stats: deterministic two-stage -------------------
// stage 1: per 128-row slab partial sum/sumsq per channel (no atomics)
__global__ void bn_stats_kernel(const float* __restrict__ Y0,
                                const float* __restrict__ Y1,
                                const float* __restrict__ Y2, int zbase)
{
    int z = blockIdx.y;
    const float* Y = (z == 0) ? Y0 : (z == 1) ? Y1 : Y2;
    int ch = threadIdx.x;                      // 0..127
    size_t r0 = (size_t)blockIdx.x * 128;
    float s = 0.f, s2 = 0.f;
    for (int r = 0; r < 128; r++) {
        float v = Y[(r0 + r) * 128 + ch];
        s += v;
        s2 += v * v;
    }
    int slot = ((zbase + z) * MBLK + blockIdx.x) * DCH + ch;
    g_psum[slot]   = s;
    g_psumsq[slot] = s2;
}

// stage 2: reduce 384 partials, compute scale/shift
__global__ void bn_finalize_kernel(const float* __restrict__ g0, const float* __restrict__ be0,
                                   const float* __restrict__ g1, const float* __restrict__ be1,
                                   const float* __restrict__ g2, const float* __restrict__ be2,
                                   int zbase, int nz)
{
    int i = threadIdx.x;
    if (i >= nz * 128) return;
    int z = i >> 7, ch = i & 127;
    const float* g  = (z == 0) ? g0 : (z == 1) ? g1 : g2;
    const float* be = (z == 0) ? be0 : (z == 1) ? be1 : be2;
    float s = 0.f, s2 = 0.f;
    for (int bkt = 0; bkt < MBLK; bkt++) {
        int slot = ((zbase + z) * MBLK + bkt) * DCH + ch;
        s  += g_psum[slot];
        s2 += g_psumsq[slot];
    }
    const float inv_cnt = 1.f / (float)ROWS;
    float mu  = s * inv_cnt;
    float var = s2 * inv_cnt - mu * mu;
    float sc  = g[ch] * rsqrtf(var + 1e-5f);
    g_scale[(zbase + z) * 128 + ch] = sc;
    g_shift[(zbase + z) * 128 + ch] = be[ch] - mu * sc;
}

// ---------------- sparse masked attention -----------------------------------
// grid (96, 4) = (b*T+t, head); block 512 threads = 16 warps, warp per row.
// BN+ReLU for q/k/v fused into loads. Masked scores underflow to exact 0 in
// fp32 softmax, so only A>0 neighbors (CSR) are evaluated.
__global__ void attn_kernel()
{
    extern __shared__ float sm[];
    const int bt   = blockIdx.x;
    const int h    = blockIdx.y;
    const int tid  = threadIdx.x;
    const int nw   = blockDim.x >> 5;
    const int wid  = tid >> 5;
    const int lane = tid & 31;

    float* Ks = sm;                               // [512][33] padded
    float* Vs = sm + 512 * 33;                    // [512][33]
    float* ps = sm + 2 * 512 * 33 + wid * 512;    // per-warp probs
    float* qs = sm + 2 * 512 * 33 + nw * 512 + wid * 32;  // per-warp q row

    const size_t rowbase = (size_t)bt * NNODES;
    const int cb = h * 32;

    // per-channel BN params (channel == lane for this head)
    const float scq = g_scale[0 * 128 + cb + lane], shq = g_shift[0 * 128 + cb + lane];
    const float sck = g_scale[1 * 128 + cb + lane], shk = g_shift[1 * 128 + cb + lane];
    const float scv = g_scale[2 * 128 + cb + lane], shv = g_shift[2 * 128 + cb + lane];

    // stage K,V head slices into smem with fused BN+ReLU (coalesced 128B/warp)
    for (int idx = tid; idx < NNODES * 32; idx += blockDim.x) {
        int m = idx >> 5;                          // (idx&31) == lane
        float kv = g_kraw[(rowbase + m) * 128 + cb + lane];
        Ks[m * 33 + lane] = fmaxf(0.f, fmaf(kv, sck, shk));
        float vv = g_vraw[(rowbase + m) * 128 + cb + lane];
        Vs[m * 33 + lane] = fmaxf(0.f, fmaf(vv, scv, shv));
    }
    __syncthreads();

    for (int n = wid; n < NNODES; n += nw) {
        const int cnt = g_cnt[n];
        const int* nb = g_nbr + n * NNODES;

        float qv = g_qraw[(rowbase + n) * 128 + cb + lane];
        qs[lane] = fmaxf(0.f, fmaf(qv, scq, shq));
        __syncwarp();

        // pass 1: scores for this row's neighbors (lane-parallel over neighbors)
        float mx = -3.0e38f;
        for (int c = lane; c < cnt; c += 32) {
            int m = nb[c];
            const float* kp = Ks + m * 33;
            float s = 0.f;
#pragma unroll
            for (int j = 0; j < 32; j++) s = fmaf(qs[j], kp[j], s);
            s *= 0.5f;                 // 1/sqrt(d), d=4
            ps[c] = s;
            mx = fmaxf(mx, s);
        }
#pragma unroll
        for (int o = 16; o > 0; o >>= 1)
            mx = fmaxf(mx, __shfl_xor_sync(0xffffffffu, mx, o));

        // pass 2: exp + sum
        float sum = 0.f;
        for (int c = lane; c < cnt; c += 32) {
            float p = __expf(ps[c] - mx);
            ps[c] = p;
            sum += p;
        }
#pragma unroll
        for (int o = 16; o > 0; o >>= 1)
            sum += __shfl_xor_sync(0xffffffffu, sum, o);
        float inv = 1.f / sum;
        __syncwarp();   // ps writes visible to all lanes

        // pass 3: out[lane] = sum_c p_c * V[m_c][lane]
        float acc = 0.f;
        for (int c = 0; c < cnt; c++) {
            int m = nb[c];
            acc = fmaf(ps[c], Vs[m * 33 + lane], acc);
        }
        g_aout[(rowbase + n) * 128 + cb + lane] = acc * inv;
        __syncwarp();   // protect qs/ps before next row reuses them
    }
}

// ---------------- final BN+ReLU into d_out -----------------------------------
__global__ void bn_apply_kernel(float* __restrict__ out)
{
    size_t i = (size_t)blockIdx.x * blockDim.x + threadIdx.x;
    if (i >= (size_t)ROWS * DCH) return;
    int ch = (int)(i & 127);
    out[i] = fmaxf(0.f, fmaf(g_oraw[i], g_scale[3 * 128 + ch], g_shift[3 * 128 + ch]));
}

// =============================================================================
extern "C" void kernel_launch(void* const* d_in, const int* in_sizes, int n_in,
                              void* d_out, int out_size)
{
    (void)in_sizes; (void)n_in; (void)out_size;
    const float* X     = (const float*)d_in[0];
    const float* STE   = (const float*)d_in[1];
    const float* A     = (const float*)d_in[2];
    const float* Wq    = (const float*)d_in[3];
    const float* bq    = (const float*)d_in[4];
    const float* gq    = (const float*)d_in[5];
    const float* betaq = (const float*)d_in[6];
    const float* Wk    = (const float*)d_in[7];
    const float* bk    = (const float*)d_in[8];
    const float* gk    = (const float*)d_in[9];
    const float* betak = (const float*)d_in[10];
    const float* Wv    = (const float*)d_in[11];
    const float* bv    = (const float*)d_in[12];
    const float* gv    = (const float*)d_in[13];
    const float* betav = (const float*)d_in[14];
    const float* Wo    = (const float*)d_in[15];
    const float* bo    = (const float*)d_in[16];
    const float* go    = (const float*)d_in[17];
    const float* betao = (const float*)d_in[18];
    float* out = (float*)d_out;

    void *pq, *pk, *pv, *pa, *po;
    cudaGetSymbolAddress(&pq, g_qraw);
    cudaGetSymbolAddress(&pk, g_kraw);
    cudaGetSymbolAddress(&pv, g_vraw);
    cudaGetSymbolAddress(&pa, g_aout);
    cudaGetSymbolAddress(&po, g_oraw);

    const int smem_attn = (2 * 512 * 33 + 16 * 512 + 16 * 32) * (int)sizeof(float); // ~166 KB
    cudaFuncSetAttribute(attn_kernel, cudaFuncAttributeMaxDynamicSharedMemorySize,
                         smem_attn);

    // 1) adjacency -> CSR
    build_csr_kernel<<<16, 1024>>>(A);

    // 2) q/k/v projections: Y = [X|STE] @ W + b   (raw, BN applied later)
    gemm_kernel<256, true><<<dim3(MBLK, 1, 3), 256>>>(
        X, STE, Wq, Wk, Wv, bq, bk, bv,
        (float*)pq, (float*)pk, (float*)pv);

    // 3) BN batch stats for q/k/v (deterministic)
    bn_stats_kernel<<<dim3(MBLK, 3), 128>>>((float*)pq, (float*)pk, (float*)pv, 0);
    bn_finalize_kernel<<<1, 512>>>(gq, betaq, gk, betak, gv, betav, 0, 3);

    // 4) sparse masked attention (BN+ReLU fused into q/k/v loads)
    attn_kernel<<<dim3(NBT, NH), 512, smem_attn>>>();

    // 5) output projection
    gemm_kernel<128, false><<<dim3(MBLK, 1, 1), 256>>>(
        (float*)pa, nullptr, Wo, Wo, Wo, bo, bo, bo,
        (float*)po, (float*)po, (float*)po);

    // 6) BN stats + finalize for output
    bn_stats_kernel<<<dim3(MBLK, 1), 128>>>((float*)po, (float*)po, (float*)po, 3);
    bn_finalize_kernel<<<1, 128>>>(go, betao, go, betao, go, betao, 3, 1);

    // 7) BN + ReLU -> d_out
    bn_apply_kernel<<<(ROWS * DCH + 255) / 256, 256>>>(out);
}

// round 4
// speedup vs baseline: 1.4626x; 1.4626x over previous
#include <cuda_runtime.h>
#include <math.h>

// Problem constants
#define ROWS   49152      // B*T*N = 8*12*512
#define DCH    128        // D
#define NNODES 512        // N
#define NBT    96         // B*T
#define NH     4          // heads (d)
#define MBLK   384        // ROWS / 128

// ---------------- scratch (device globals; no cudaMalloc allowed) ----------
__device__ float g_qraw[ROWS * DCH];
__device__ float g_kraw[ROWS * DCH];
__device__ float g_vraw[ROWS * DCH];
__device__ float g_aout[ROWS * DCH];
__device__ float g_oraw[ROWS * DCH];
__device__ int   g_nbr[NNODES * NNODES];
__device__ int   g_cnt[NNODES];
// deterministic BN partials: [z in 0..3][block 0..383][ch 0..127]
__device__ float g_psum[4 * MBLK * DCH];
__device__ float g_psumsq[4 * MBLK * DCH];
__device__ float g_scale[4 * DCH];
__device__ float g_shift[4 * DCH];

// ---------------- helpers ----------------------------------------------------
__device__ __forceinline__ unsigned f2tf32(float f) {
    unsigned r;
    asm("cvt.rna.tf32.f32 %0, %1;" : "=r"(r) : "f"(f));
    return r;
}

__device__ __forceinline__ void mma_tf32(float* c, const unsigned* a, const unsigned* b) {
    asm volatile(
        "mma.sync.aligned.m16n8k8.row.col.f32.tf32.tf32.f32 "
        "{%0,%1,%2,%3}, {%4,%5,%6,%7}, {%8,%9}, {%0,%1,%2,%3};\n"
        : "+f"(c[0]), "+f"(c[1]), "+f"(c[2]), "+f"(c[3])
        : "r"(a[0]), "r"(a[1]), "r"(a[2]), "r"(a[3]), "r"(b[0]), "r"(b[1]));
}

// ---------------- CSR build of adjacency (warp per row, ballot compaction) --
__global__ void build_csr_kernel(const float* __restrict__ A)
{
    int warp = (blockIdx.x * blockDim.x + threadIdx.x) >> 5;
    int lane = threadIdx.x & 31;
    if (warp >= NNODES) return;
    int base = 0;
    for (int m0 = 0; m0 < NNODES; m0 += 32) {
        float a = A[warp * NNODES + m0 + lane];
        unsigned bal = __ballot_sync(0xffffffffu, a > 0.f);
        if (a > 0.f) {
            int pre = __popc(bal & ((1u << lane) - 1u));
            g_nbr[warp * NNODES + base + pre] = m0 + lane;
        }
        base += __popc(bal);
    }
    if (lane == 0) g_cnt[warp] = base;
}

// ---------------- tf32 tensor-core GEMM, 128x128 tile, BK=32 ----------------
// Y = A @ W  (bias dropped: it cancels exactly in the following BatchNorm).
// CAT=true: logical A row = [X_row(128) | STE_row(128)], KDIM=256.
// Fused epilogue: per-CTA per-channel sum/sumsq partials -> g_psum/g_psumsq.
// 256 threads = 8 warps as 2(m) x 4(n); warp tile 64x32; thread does 4x4 mmas.
template <int KDIM, bool CAT>
__global__ __launch_bounds__(256)
void mma_gemm_kernel(const float* __restrict__ A0, const float* __restrict__ A1,
                     const float* __restrict__ W0, const float* __restrict__ W1,
                     const float* __restrict__ W2,
                     float* __restrict__ Y0, float* __restrict__ Y1,
                     float* __restrict__ Y2, int zbase)
{
    __shared__ unsigned As[128 * 36];   // [row][k] pad 36 -> conflict-free frags
    __shared__ unsigned Bs[32 * 136];   // [k][n]  pad 136 -> conflict-free frags
    __shared__ float ssum[2][128], ssq[2][128];

    const int z = blockIdx.z;
    const float* W = (z == 0) ? W0 : (z == 1) ? W1 : W2;
    float*       Y = (z == 0) ? Y0 : (z == 1) ? Y1 : Y2;

    const int tid  = threadIdx.x;
    const int lane = tid & 31;
    const int wid  = tid >> 5;
    const int wm   = wid >> 2;           // 0..1  (64-row slab)
    const int wn   = wid & 3;            // 0..3  (32-col slab)
    const int row0 = blockIdx.x * 128;
    const int g    = lane >> 2;          // group id 0..7
    const int tg   = lane & 3;           // thread-in-group 0..3

    float acc[4][4][4];
#pragma unroll
    for (int mt = 0; mt < 4; mt++)
#pragma unroll
        for (int nt = 0; nt < 4; nt++)
#pragma unroll
            for (int q = 0; q < 4; q++) acc[mt][nt][q] = 0.f;

    for (int k0 = 0; k0 < KDIM; k0 += 32) {
        const float* Abase;
        int kofs;
        if (CAT) {
            if (k0 < 128) { Abase = A0; kofs = k0; }
            else          { Abase = A1; kofs = k0 - 128; }
        } else { Abase = A0; kofs = k0; }

        // A tile: 128 rows x 32 k = 1024 float4, 4 per thread
#pragma unroll
        for (int t = 0; t < 4; t++) {
            int i  = tid + 256 * t;
            int r  = i >> 3;
            int kq = (i & 7) << 2;
            float4 v = *(const float4*)(Abase + (size_t)(row0 + r) * 128 + kofs + kq);
            unsigned* d = &As[r * 36 + kq];
            d[0] = f2tf32(v.x); d[1] = f2tf32(v.y);
            d[2] = f2tf32(v.z); d[3] = f2tf32(v.w);
        }
        // B tile: 32 k x 128 n = 1024 float4
#pragma unroll
        for (int t = 0; t < 4; t++) {
            int i  = tid + 256 * t;
            int k  = i >> 5;
            int n4 = (i & 31) << 2;
            float4 v = *(const float4*)(W + (size_t)(k0 + k) * 128 + n4);
            unsigned* d = &Bs[k * 136 + n4];
            d[0] = f2tf32(v.x); d[1] = f2tf32(v.y);
            d[2] = f2tf32(v.z); d[3] = f2tf32(v.w);
        }
        __syncthreads();

#pragma unroll
        for (int ks = 0; ks < 4; ks++) {
            const int kb = ks * 8;
            unsigned af[4][4];
#pragma unroll
            for (int mt = 0; mt < 4; mt++) {
                int r = wm * 64 + mt * 16 + g;
                af[mt][0] = As[r * 36 + kb + tg];
                af[mt][1] = As[(r + 8) * 36 + kb + tg];
                af[mt][2] = As[r * 36 + kb + tg + 4];
                af[mt][3] = As[(r + 8) * 36 + kb + tg + 4];
            }
            unsigned bf[4][2];
#pragma unroll
            for (int nt = 0; nt < 4; nt++) {
                int c = wn * 32 + nt * 8 + g;
                bf[nt][0] = Bs[(kb + tg) * 136 + c];
                bf[nt][1] = Bs[(kb + tg + 4) * 136 + c];
            }
#pragma unroll
            for (int mt = 0; mt < 4; mt++)
#pragma unroll
                for (int nt = 0; nt < 4; nt++)
                    mma_tf32(acc[mt][nt], af[mt], bf[nt]);
        }
        __syncthreads();
    }

    // -------- epilogue: store Y + fused per-CTA BN partial stats ------------
#pragma unroll
    for (int nt = 0; nt < 4; nt++) {
        float se = 0.f, so = 0.f, qe = 0.f, qo = 0.f;
#pragma unroll
        for (int mt = 0; mt < 4; mt++) {
            float c0 = acc[mt][nt][0], c1 = acc[mt][nt][1];
            float c2 = acc[mt][nt][2], c3 = acc[mt][nt][3];
            int r   = row0 + wm * 64 + mt * 16 + g;
            int col = wn * 32 + nt * 8 + tg * 2;
            float2 v0 = make_float2(c0, c1);
            float2 v1 = make_float2(c2, c3);
            *(float2*)(Y + (size_t)r * 128 + col)       = v0;
            *(float2*)(Y + (size_t)(r + 8) * 128 + col) = v1;
            se += c0 + c2;  so += c1 + c3;
            qe += c0 * c0 + c2 * c2;  qo += c1 * c1 + c3 * c3;
        }
        // reduce over the 8 row-groups (lanes differing in bits 2..4)
#pragma unroll
        for (int o = 4; o < 32; o <<= 1) {
            se += __shfl_xor_sync(0xffffffffu, se, o);
            so += __shfl_xor_sync(0xffffffffu, so, o);
            qe += __shfl_xor_sync(0xffffffffu, qe, o);
            qo += __shfl_xor_sync(0xffffffffu, qo, o);
        }
        if (lane < 4) {
            int col = wn * 32 + nt * 8 + lane * 2;
            ssum[wm][col]     = se;  ssum[wm][col + 1] = so;
            ssq[wm][col]      = qe;  ssq[wm][col + 1]  = qo;
        }
    }
    __syncthreads();
    if (tid < 128) {
        int slot = ((zbase + z) * MBLK + blockIdx.x) * DCH + tid;
        g_psum[slot]   = ssum[0][tid] + ssum[1][tid];
        g_psumsq[slot] = ssq[0][tid] + ssq[1][tid];
    }
}

// ---------------- BN finalize: reduce 384 partials (parallel) ---------------
__global__ void bn_finalize_kernel(const float* __restrict__ g0, const float* __restrict__ be0,
                                   const float* __restrict__ g1, const float* __restrict__ be1,
                                   const float* __restrict__ g2, const float* __restrict__ be2,
                                   int zbase)
{
    __shared__ float ss[512], sq[512];
    int z = blockIdx.x;
    const float* g  = (z == 0) ? g0 : (z == 1) ? g1 : g2;
    const float* be = (z == 0) ? be0 : (z == 1) ? be1 : be2;
    int ch = threadIdx.x & 127, part = threadIdx.x >> 7;   // 4 parts
    float s = 0.f, s2 = 0.f;
    for (int b = part; b < MBLK; b += 4) {
        int slot = ((zbase + z) * MBLK + b) * DCH + ch;
        s  += g_psum[slot];
        s2 += g_psumsq[slot];
    }
    ss[threadIdx.x] = s;  sq[threadIdx.x] = s2;
    __syncthreads();
    if (threadIdx.x < 128) {
        s  = ss[ch] + ss[ch + 128] + ss[ch + 256] + ss[ch + 384];
        s2 = sq[ch] + sq[ch + 128] + sq[ch + 256] + sq[ch + 384];
        const float inv_cnt = 1.f / (float)ROWS;
        float mu  = s * inv_cnt;
        float var = s2 * inv_cnt - mu * mu;
        float sc  = g[ch] * rsqrtf(var + 1e-5f);
        g_scale[(zbase + z) * 128 + ch] = sc;
        g_shift[(zbase + z) * 128 + ch] = be[ch] - mu * sc;
    }
}

// ---------------- sparse masked attention -----------------------------------
// grid (96, 4) = (b*T+t, head); block 512 threads = 16 warps, warp per row.
// BN+ReLU for q/k/v fused into loads. Masked scores underflow to exact 0 in
// fp32 softmax, so only A>0 neighbors (CSR) are evaluated.
__global__ void attn_kernel()
{
    extern __shared__ float sm[];
    const int bt   = blockIdx.x;
    const int h    = blockIdx.y;
    const int tid  = threadIdx.x;
    const int nw   = blockDim.x >> 5;
    const int wid  = tid >> 5;
    const int lane = tid & 31;

    float* Ks = sm;                               // [512][33] padded
    float* Vs = sm + 512 * 33;                    // [512][33]
    float* ps = sm + 2 * 512 * 33 + wid * 512;    // per-warp probs
    float* qs = sm + 2 * 512 * 33 + nw * 512 + wid * 32;  // per-warp q row

    const size_t rowbase = (size_t)bt * NNODES;
    const int cb = h * 32;

    const float scq = g_scale[0 * 128 + cb + lane], shq = g_shift[0 * 128 + cb + lane];
    const float sck = g_scale[1 * 128 + cb + lane], shk = g_shift[1 * 128 + cb + lane];
    const float scv = g_scale[2 * 128 + cb + lane], shv = g_shift[2 * 128 + cb + lane];

    for (int idx = tid; idx < NNODES * 32; idx += blockDim.x) {
        int m = idx >> 5;                          // (idx&31) == lane
        float kv = g_kraw[(rowbase + m) * 128 + cb + lane];
        Ks[m * 33 + lane] = fmaxf(0.f, fmaf(kv, sck, shk));
        float vv = g_vraw[(rowbase + m) * 128 + cb + lane];
        Vs[m * 33 + lane] = fmaxf(0.f, fmaf(vv, scv, shv));
    }
    __syncthreads();

    for (int n = wid; n < NNODES; n += nw) {
        const int cnt = g_cnt[n];
        const int* nb = g_nbr + n * NNODES;

        float qv = g_qraw[(rowbase + n) * 128 + cb + lane];
        qs[lane] = fmaxf(0.f, fmaf(qv, scq, shq));
        __syncwarp();

        float mx = -3.0e38f;
        for (int c = lane; c < cnt; c += 32) {
            int m = nb[c];
            const float* kp = Ks + m * 33;
            float s = 0.f;
#pragma unroll
            for (int j = 0; j < 32; j++) s = fmaf(qs[j], kp[j], s);
            s *= 0.5f;                 // 1/sqrt(d), d=4
            ps[c] = s;
            mx = fmaxf(mx, s);
        }
#pragma unroll
        for (int o = 16; o > 0; o >>= 1)
            mx = fmaxf(mx, __shfl_xor_sync(0xffffffffu, mx, o));

        float sum = 0.f;
        for (int c = lane; c < cnt; c += 32) {
            float p = __expf(ps[c] - mx);
            ps[c] = p;
            sum += p;
        }
#pragma unroll
        for (int o = 16; o > 0; o >>= 1)
            sum += __shfl_xor_sync(0xffffffffu, sum, o);
        float inv = 1.f / sum;
        __syncwarp();

        float accv = 0.f;
        for (int c = 0; c < cnt; c++) {
            int m = nb[c];
            accv = fmaf(ps[c], Vs[m * 33 + lane], accv);
        }
        g_aout[(rowbase + n) * 128 + cb + lane] = accv * inv;
        __syncwarp();
    }
}

// ---------------- final BN+ReLU into d_out -----------------------------------
__global__ void bn_apply_kernel(float* __restrict__ out)
{
    size_t i = (size_t)blockIdx.x * blockDim.x + threadIdx.x;
    if (i >= (size_t)ROWS * DCH) return;
    int ch = (int)(i & 127);
    out[i] = fmaxf(0.f, fmaf(g_oraw[i], g_scale[3 * 128 + ch], g_shift[3 * 128 + ch]));
}

// =============================================================================
extern "C" void kernel_launch(void* const* d_in, const int* in_sizes, int n_in,
                              void* d_out, int out_size)
{
    (void)in_sizes; (void)n_in; (void)out_size;
    const float* X     = (const float*)d_in[0];
    const float* STE   = (const float*)d_in[1];
    const float* A     = (const float*)d_in[2];
    const float* Wq    = (const float*)d_in[3];
    const float* gq    = (const float*)d_in[5];
    const float* betaq = (const float*)d_in[6];
    const float* Wk    = (const float*)d_in[7];
    const float* gk    = (const float*)d_in[9];
    const float* betak = (const float*)d_in[10];
    const float* Wv    = (const float*)d_in[11];
    const float* gv    = (const float*)d_in[13];
    const float* betav = (const float*)d_in[14];
    const float* Wo    = (const float*)d_in[15];
    const float* go    = (const float*)d_in[17];
    const float* betao = (const float*)d_in[18];
    float* out = (float*)d_out;

    void *pq, *pk, *pv, *pa, *po;
    cudaGetSymbolAddress(&pq, g_qraw);
    cudaGetSymbolAddress(&pk, g_kraw);
    cudaGetSymbolAddress(&pv, g_vraw);
    cudaGetSymbolAddress(&pa, g_aout);
    cudaGetSymbolAddress(&po, g_oraw);

    const int smem_attn = (2 * 512 * 33 + 16 * 512 + 16 * 32) * (int)sizeof(float); // ~166 KB
    cudaFuncSetAttribute(attn_kernel, cudaFuncAttributeMaxDynamicSharedMemorySize,
                         smem_attn);

    // 1) adjacency -> CSR
    build_csr_kernel<<<16, 1024>>>(A);

    // 2) q/k/v projections (tf32 tensor cores, fused BN partial stats; bias
    //    dropped: it cancels exactly in BatchNorm)
    mma_gemm_kernel<256, true><<<dim3(MBLK, 1, 3), 256>>>(
        X, STE, Wq, Wk, Wv, (float*)pq, (float*)pk, (float*)pv, 0);

    // 3) BN finalize for q/k/v (parallel)
    bn_finalize_kernel<<<3, 512>>>(gq, betaq, gk, betak, gv, betav, 0);

    // 4) sparse masked attention (BN+ReLU fused into q/k/v loads)
    attn_kernel<<<dim3(NBT, NH), 512, smem_attn>>>();

    // 5) output projection (fused BN partial stats)
    mma_gemm_kernel<128, false><<<dim3(MBLK, 1, 1), 256>>>(
        (float*)pa, nullptr, Wo, Wo, Wo, (float*)po, (float*)po, (float*)po, 3);

    // 6) BN finalize for output
    bn_finalize_kernel<<<1, 512>>>(go, betao, go, betao, go, betao, 3);

    // 7) BN + ReLU -> d_out
    bn_apply_kernel<<<(ROWS * DCH + 255) / 256, 256>>>(out);
}

// round 5
// speedup vs baseline: 1.5479x; 1.0583x over previous
#include <cuda_runtime.h>
#include <math.h>

// Problem constants
#define ROWS   49152      // B*T*N = 8*12*512
#define DCH    128        // D
#define NNODES 512        // N
#define NBT    96         // B*T
#define NH     4          // heads (d)
#define MBLK   384        // ROWS / 128
#define KVSTRIDE 36       // padded row stride (floats) for Ks/Vs, 16B-aligned

// ---------------- scratch (device globals; no cudaMalloc allowed) ----------
__device__ float g_qraw[ROWS * DCH];
__device__ float g_kraw[ROWS * DCH];
__device__ float g_vraw[ROWS * DCH];
__device__ float g_aout[ROWS * DCH];
__device__ float g_oraw[ROWS * DCH];
__device__ int   g_nbr[NNODES * NNODES];
__device__ int   g_cnt[NNODES];
// deterministic BN partials: [z in 0..3][block 0..383][ch 0..127]
__device__ float g_psum[4 * MBLK * DCH];
__device__ float g_psumsq[4 * MBLK * DCH];
__device__ float g_scale[4 * DCH];
__device__ float g_shift[4 * DCH];

// ---------------- helpers ----------------------------------------------------
__device__ __forceinline__ unsigned f2tf32(float f) {
    unsigned r;
    asm("cvt.rna.tf32.f32 %0, %1;" : "=r"(r) : "f"(f));
    return r;
}

__device__ __forceinline__ void mma_tf32(float* c, const unsigned* a, const unsigned* b) {
    asm volatile(
        "mma.sync.aligned.m16n8k8.row.col.f32.tf32.tf32.f32 "
        "{%0,%1,%2,%3}, {%4,%5,%6,%7}, {%8,%9}, {%0,%1,%2,%3};\n"
        : "+f"(c[0]), "+f"(c[1]), "+f"(c[2]), "+f"(c[3])
        : "r"(a[0]), "r"(a[1]), "r"(a[2]), "r"(a[3]), "r"(b[0]), "r"(b[1]));
}

// ---------------- CSR build of adjacency (warp per row, ballot compaction) --
__global__ void build_csr_kernel(const float* __restrict__ A)
{
    int warp = (blockIdx.x * blockDim.x + threadIdx.x) >> 5;
    int lane = threadIdx.x & 31;
    if (warp >= NNODES) return;
    int base = 0;
    for (int m0 = 0; m0 < NNODES; m0 += 32) {
        float a = A[warp * NNODES + m0 + lane];
        unsigned bal = __ballot_sync(0xffffffffu, a > 0.f);
        if (a > 0.f) {
            int pre = __popc(bal & ((1u << lane) - 1u));
            g_nbr[warp * NNODES + base + pre] = m0 + lane;
        }
        base += __popc(bal);
    }
    if (lane == 0) g_cnt[warp] = base;
}

// ---------------- tf32 tensor-core GEMM, 128x128 tile, BK=32 ----------------
// Y = A @ W  (bias dropped: it cancels exactly in the following BatchNorm).
// CAT=true: logical A row = [X_row(128) | STE_row(128)], KDIM=256.
// Fused epilogue: per-CTA per-channel sum/sumsq partials -> g_psum/g_psumsq.
template <int KDIM, bool CAT>
__global__ __launch_bounds__(256)
void mma_gemm_kernel(const float* __restrict__ A0, const float* __restrict__ A1,
                     const float* __restrict__ W0, const float* __restrict__ W1,
                     const float* __restrict__ W2,
                     float* __restrict__ Y0, float* __restrict__ Y1,
                     float* __restrict__ Y2, int zbase)
{
    __shared__ unsigned As[128 * 36];
    __shared__ unsigned Bs[32 * 136];
    __shared__ float ssum[2][128], ssq[2][128];

    const int z = blockIdx.z;
    const float* W = (z == 0) ? W0 : (z == 1) ? W1 : W2;
    float*       Y = (z == 0) ? Y0 : (z == 1) ? Y1 : Y2;

    const int tid  = threadIdx.x;
    const int lane = tid & 31;
    const int wid  = tid >> 5;
    const int wm   = wid >> 2;
    const int wn   = wid & 3;
    const int row0 = blockIdx.x * 128;
    const int g    = lane >> 2;
    const int tg   = lane & 3;

    float acc[4][4][4];
#pragma unroll
    for (int mt = 0; mt < 4; mt++)
#pragma unroll
        for (int nt = 0; nt < 4; nt++)
#pragma unroll
            for (int q = 0; q < 4; q++) acc[mt][nt][q] = 0.f;

    for (int k0 = 0; k0 < KDIM; k0 += 32) {
        const float* Abase;
        int kofs;
        if (CAT) {
            if (k0 < 128) { Abase = A0; kofs = k0; }
            else          { Abase = A1; kofs = k0 - 128; }
        } else { Abase = A0; kofs = k0; }

#pragma unroll
        for (int t = 0; t < 4; t++) {
            int i  = tid + 256 * t;
            int r  = i >> 3;
            int kq = (i & 7) << 2;
            float4 v = *(const float4*)(Abase + (size_t)(row0 + r) * 128 + kofs + kq);
            unsigned* d = &As[r * 36 + kq];
            d[0] = f2tf32(v.x); d[1] = f2tf32(v.y);
            d[2] = f2tf32(v.z); d[3] = f2tf32(v.w);
        }
#pragma unroll
        for (int t = 0; t < 4; t++) {
            int i  = tid + 256 * t;
            int k  = i >> 5;
            int n4 = (i & 31) << 2;
            float4 v = *(const float4*)(W + (size_t)(k0 + k) * 128 + n4);
            unsigned* d = &Bs[k * 136 + n4];
            d[0] = f2tf32(v.x); d[1] = f2tf32(v.y);
            d[2] = f2tf32(v.z); d[3] = f2tf32(v.w);
        }
        __syncthreads();

#pragma unroll
        for (int ks = 0; ks < 4; ks++) {
            const int kb = ks * 8;
            unsigned af[4][4];
#pragma unroll
            for (int mt = 0; mt < 4; mt++) {
                int r = wm * 64 + mt * 16 + g;
                af[mt][0] = As[r * 36 + kb + tg];
                af[mt][1] = As[(r + 8) * 36 + kb + tg];
                af[mt][2] = As[r * 36 + kb + tg + 4];
                af[mt][3] = As[(r + 8) * 36 + kb + tg + 4];
            }
            unsigned bf[4][2];
#pragma unroll
            for (int nt = 0; nt < 4; nt++) {
                int c = wn * 32 + nt * 8 + g;
                bf[nt][0] = Bs[(kb + tg) * 136 + c];
                bf[nt][1] = Bs[(kb + tg + 4) * 136 + c];
            }
#pragma unroll
            for (int mt = 0; mt < 4; mt++)
#pragma unroll
                for (int nt = 0; nt < 4; nt++)
                    mma_tf32(acc[mt][nt], af[mt], bf[nt]);
        }
        __syncthreads();
    }

#pragma unroll
    for (int nt = 0; nt < 4; nt++) {
        float se = 0.f, so = 0.f, qe = 0.f, qo = 0.f;
#pragma unroll
        for (int mt = 0; mt < 4; mt++) {
            float c0 = acc[mt][nt][0], c1 = acc[mt][nt][1];
            float c2 = acc[mt][nt][2], c3 = acc[mt][nt][3];
            int r   = row0 + wm * 64 + mt * 16 + g;
            int col = wn * 32 + nt * 8 + tg * 2;
            *(float2*)(Y + (size_t)r * 128 + col)       = make_float2(c0, c1);
            *(float2*)(Y + (size_t)(r + 8) * 128 + col) = make_float2(c2, c3);
            se += c0 + c2;  so += c1 + c3;
            qe += c0 * c0 + c2 * c2;  qo += c1 * c1 + c3 * c3;
        }
#pragma unroll
        for (int o = 4; o < 32; o <<= 1) {
            se += __shfl_xor_sync(0xffffffffu, se, o);
            so += __shfl_xor_sync(0xffffffffu, so, o);
            qe += __shfl_xor_sync(0xffffffffu, qe, o);
            qo += __shfl_xor_sync(0xffffffffu, qo, o);
        }
        if (lane < 4) {
            int col = wn * 32 + nt * 8 + lane * 2;
            ssum[wm][col]     = se;  ssum[wm][col + 1] = so;
            ssq[wm][col]      = qe;  ssq[wm][col + 1]  = qo;
        }
    }
    __syncthreads();
    if (tid < 128) {
        int slot = ((zbase + z) * MBLK + blockIdx.x) * DCH + tid;
        g_psum[slot]   = ssum[0][tid] + ssum[1][tid];
        g_psumsq[slot] = ssq[0][tid] + ssq[1][tid];
    }
}

// ---------------- BN finalize: reduce 384 partials (parallel) ---------------
__global__ void bn_finalize_kernel(const float* __restrict__ g0, const float* __restrict__ be0,
                                   const float* __restrict__ g1, const float* __restrict__ be1,
                                   const float* __restrict__ g2, const float* __restrict__ be2,
                                   int zbase)
{
    __shared__ float ss[512], sq[512];
    int z = blockIdx.x;
    const float* g  = (z == 0) ? g0 : (z == 1) ? g1 : g2;
    const float* be = (z == 0) ? be0 : (z == 1) ? be1 : be2;
    int ch = threadIdx.x & 127, part = threadIdx.x >> 7;
    float s = 0.f, s2 = 0.f;
    for (int b = part; b < MBLK; b += 4) {
        int slot = ((zbase + z) * MBLK + b) * DCH + ch;
        s  += g_psum[slot];
        s2 += g_psumsq[slot];
    }
    ss[threadIdx.x] = s;  sq[threadIdx.x] = s2;
    __syncthreads();
    if (threadIdx.x < 128) {
        s  = ss[ch] + ss[ch + 128] + ss[ch + 256] + ss[ch + 384];
        s2 = sq[ch] + sq[ch + 128] + sq[ch + 256] + sq[ch + 384];
        const float inv_cnt = 1.f / (float)ROWS;
        float mu  = s * inv_cnt;
        float var = s2 * inv_cnt - mu * mu;
        float sc  = g[ch] * rsqrtf(var + 1e-5f);
        g_scale[(zbase + z) * 128 + ch] = sc;
        g_shift[(zbase + z) * 128 + ch] = be[ch] - mu * sc;
    }
}

// ---------------- sparse masked attention: one-pass online softmax ----------
// grid (96, 4) = (b*T+t, head); block 1024 threads = 32 warps, warp per row.
// Per 32-neighbor chunk: lane = neighbor for scores (float4 LDS dot),
// lane = channel for the V gather (p/m broadcast via shfl, fully unrolled).
// Masked scores underflow to exact 0, so only A>0 neighbors are evaluated.
__global__ __launch_bounds__(1024)
void attn_kernel()
{
    extern __shared__ float sm[];
    const int bt   = blockIdx.x;
    const int h    = blockIdx.y;
    const int tid  = threadIdx.x;
    const int wid  = tid >> 5;
    const int lane = tid & 31;

    float* Ks = sm;                                   // [512][36]
    float* Vs = sm + NNODES * KVSTRIDE;               // [512][36]
    float* qs = sm + 2 * NNODES * KVSTRIDE + wid * 32; // per-warp q row

    const size_t rowbase = (size_t)bt * NNODES;
    const int cb = h * 32;

    const float scq = g_scale[0 * 128 + cb + lane], shq = g_shift[0 * 128 + cb + lane];
    const float sck = g_scale[1 * 128 + cb + lane], shk = g_shift[1 * 128 + cb + lane];
    const float scv = g_scale[2 * 128 + cb + lane], shv = g_shift[2 * 128 + cb + lane];

    // stage K,V head slices into smem with fused BN+ReLU
    for (int idx = tid; idx < NNODES * 32; idx += 1024) {
        int m = idx >> 5;                              // (idx&31) == lane
        float kv = g_kraw[(rowbase + m) * 128 + cb + lane];
        Ks[m * KVSTRIDE + lane] = fmaxf(0.f, fmaf(kv, sck, shk));
        float vv = g_vraw[(rowbase + m) * 128 + cb + lane];
        Vs[m * KVSTRIDE + lane] = fmaxf(0.f, fmaf(vv, scv, shv));
    }
    __syncthreads();

    const float4* qp4 = (const float4*)qs;

    for (int n = wid; n < NNODES; n += 32) {
        const int cnt = g_cnt[n];
        const int* nb = g_nbr + n * NNODES;

        float qv = g_qraw[(rowbase + n) * 128 + cb + lane];
        qs[lane] = fmaxf(0.f, fmaf(qv, scq, shq));
        __syncwarp();

        float run_max = -3.0e38f, run_sum = 0.f;
        float acc0 = 0.f, acc1 = 0.f;

        for (int c0 = 0; c0 < cnt; c0 += 32) {
            int  c     = c0 + lane;
            bool valid = (c < cnt);
            int  m     = valid ? nb[c] : 0;

            // score: q . K[m] via float4 LDS, two partial chains
            float s = -3.0e38f;
            {
                const float4* kp4 = (const float4*)(Ks + m * KVSTRIDE);
                float t0 = 0.f, t1 = 0.f;
#pragma unroll
                for (int j4 = 0; j4 < 8; j4 += 2) {
                    float4 k0v = kp4[j4],     q0v = qp4[j4];
                    float4 k1v = kp4[j4 + 1], q1v = qp4[j4 + 1];
                    t0 = fmaf(q0v.x, k0v.x, t0); t0 = fmaf(q0v.y, k0v.y, t0);
                    t0 = fmaf(q0v.z, k0v.z, t0); t0 = fmaf(q0v.w, k0v.w, t0);
                    t1 = fmaf(q1v.x, k1v.x, t1); t1 = fmaf(q1v.y, k1v.y, t1);
                    t1 = fmaf(q1v.z, k1v.z, t1); t1 = fmaf(q1v.w, k1v.w, t1);
                }
                if (valid) s = (t0 + t1) * 0.5f;   // * 1/sqrt(d), d=4
            }

            // online softmax update
            float cmx = s;
#pragma unroll
            for (int o = 16; o > 0; o >>= 1)
                cmx = fmaxf(cmx, __shfl_xor_sync(0xffffffffu, cmx, o));
            float nmx  = fmaxf(run_max, cmx);
            float corr = __expf(run_max - nmx);     // 0 on first chunk
            float p    = valid ? __expf(s - nmx) : 0.f;
            float csum = p;
#pragma unroll
            for (int o = 16; o > 0; o >>= 1)
                csum += __shfl_xor_sync(0xffffffffu, csum, o);
            run_sum = run_sum * corr + csum;
            acc0 *= corr;  acc1 *= corr;
            run_max = nmx;

            // V gather: broadcast (p, m) from each lane; invalid lanes have p=0
#pragma unroll
            for (int j = 0; j < 32; j += 2) {
                float pj0 = __shfl_sync(0xffffffffu, p, j);
                int   mj0 = __shfl_sync(0xffffffffu, m, j);
                float pj1 = __shfl_sync(0xffffffffu, p, j + 1);
                int   mj1 = __shfl_sync(0xffffffffu, m, j + 1);
                acc0 = fmaf(pj0, Vs[mj0 * KVSTRIDE + lane], acc0);
                acc1 = fmaf(pj1, Vs[mj1 * KVSTRIDE + lane], acc1);
            }
        }

        g_aout[(rowbase + n) * 128 + cb + lane] = (acc0 + acc1) / run_sum;
        __syncwarp();   // protect qs before next row reuses it
    }
}

// ---------------- final BN+ReLU into d_out -----------------------------------
__global__ void bn_apply_kernel(float* __restrict__ out)
{
    size_t i = (size_t)blockIdx.x * blockDim.x + threadIdx.x;
    if (i >= (size_t)ROWS * DCH) return;
    int ch = (int)(i & 127);
    out[i] = fmaxf(0.f, fmaf(g_oraw[i], g_scale[3 * 128 + ch], g_shift[3 * 128 + ch]));
}

// =============================================================================
extern "C" void kernel_launch(void* const* d_in, const int* in_sizes, int n_in,
                              void* d_out, int out_size)
{
    (void)in_sizes; (void)n_in; (void)out_size;
    const float* X     = (const float*)d_in[0];
    const float* STE   = (const float*)d_in[1];
    const float* A     = (const float*)d_in[2];
    const float* Wq    = (const float*)d_in[3];
    const float* gq    = (const float*)d_in[5];
    const float* betaq = (const float*)d_in[6];
    const float* Wk    = (const float*)d_in[7];
    const float* gk    = (const float*)d_in[9];
    const float* betak = (const float*)d_in[10];
    const float* Wv    = (const float*)d_in[11];
    const float* gv    = (const float*)d_in[13];
    const float* betav = (const float*)d_in[14];
    const float* Wo    = (const float*)d_in[15];
    const float* go    = (const float*)d_in[17];
    const float* betao = (const float*)d_in[18];
    float* out = (float*)d_out;

    void *pq, *pk, *pv, *pa, *po;
    cudaGetSymbolAddress(&pq, g_qraw);
    cudaGetSymbolAddress(&pk, g_kraw);
    cudaGetSymbolAddress(&pv, g_vraw);
    cudaGetSymbolAddress(&pa, g_aout);
    cudaGetSymbolAddress(&po, g_oraw);

    const int smem_attn = (2 * NNODES * KVSTRIDE + 32 * 32) * (int)sizeof(float); // ~148 KB
    cudaFuncSetAttribute(attn_kernel, cudaFuncAttributeMaxDynamicSharedMemorySize,
                         smem_attn);

    // 1) adjacency -> CSR
    build_csr_kernel<<<16, 1024>>>(A);

    // 2) q/k/v projections (tf32 tensor cores, fused BN partial stats)
    mma_gemm_kernel<256, true><<<dim3(MBLK, 1, 3), 256>>>(
        X, STE, Wq, Wk, Wv, (float*)pq, (float*)pk, (float*)pv, 0);

    // 3) BN finalize for q/k/v (parallel)
    bn_finalize_kernel<<<3, 512>>>(gq, betaq, gk, betak, gv, betav, 0);

    // 4) sparse masked attention (one-pass online softmax, BN+ReLU fused)
    attn_kernel<<<dim3(NBT, NH), 1024, smem_attn>>>();

    // 5) output projection (fused BN partial stats)
    mma_gemm_kernel<128, false><<<dim3(MBLK, 1, 1), 256>>>(
        (float*)pa, nullptr, Wo, Wo, Wo, (float*)po, (float*)po, (float*)po, 3);

    // 6) BN finalize for output
    bn_finalize_kernel<<<1, 512>>>(go, betao, go, betao, go, betao, 3);

    // 7) BN + ReLU -> d_out
    bn_apply_kernel<<<(ROWS * DCH + 255) / 256, 256>>>(out);
}

// round 6
// speedup vs baseline: 1.9361x; 1.2509x over previous
#include <cuda_runtime.h>
#include <math.h>

// Problem constants
#define ROWS   49152      // B*T*N = 8*12*512
#define DCH    128        // D
#define NNODES 512        // N
#define NBT    96         // B*T
#define NH     4          // heads (d)
#define MBLK   384        // ROWS / 128

// attention smem layout pads
#define KTPAD 520         // Kt row stride (unsigned), [32][520]
#define VSPAD 36          // Vs row stride, [512][36]
#define AQPAD 36          // Asq row stride, [128][36]
#define PWPAD 68          // per-warp P buffer row stride, [16][68]

// ---------------- scratch (device globals; no cudaMalloc allowed) ----------
__device__ float    g_qraw[ROWS * DCH];
__device__ float    g_kraw[ROWS * DCH];
__device__ float    g_vraw[ROWS * DCH];
__device__ float    g_aout[ROWS * DCH];
__device__ float    g_oraw[ROWS * DCH];
__device__ unsigned g_mask[NNODES * 16];      // A>0 bitmap: row n, 16 words
// deterministic BN partials: [z in 0..3][block 0..383][ch 0..127]
__device__ float g_psum[4 * MBLK * DCH];
__device__ float g_psumsq[4 * MBLK * DCH];
__device__ float g_scale[4 * DCH];
__device__ float g_shift[4 * DCH];

// ---------------- helpers ----------------------------------------------------
__device__ __forceinline__ unsigned f2tf32(float f) {
    unsigned r;
    asm("cvt.rna.tf32.f32 %0, %1;" : "=r"(r) : "f"(f));
    return r;
}

__device__ __forceinline__ void mma_tf32(float* c, const unsigned* a, const unsigned* b) {
    asm volatile(
        "mma.sync.aligned.m16n8k8.row.col.f32.tf32.tf32.f32 "
        "{%0,%1,%2,%3}, {%4,%5,%6,%7}, {%8,%9}, {%0,%1,%2,%3};\n"
        : "+f"(c[0]), "+f"(c[1]), "+f"(c[2]), "+f"(c[3])
        : "r"(a[0]), "r"(a[1]), "r"(a[2]), "r"(a[3]), "r"(b[0]), "r"(b[1]));
}

// ---------------- adjacency bitmap (warp per row, ballot) --------------------
__global__ void build_mask_kernel(const float* __restrict__ A)
{
    int row  = (blockIdx.x * blockDim.x + threadIdx.x) >> 5;
    int lane = threadIdx.x & 31;
    if (row >= NNODES) return;
    for (int w = 0; w < 16; w++) {
        float a = A[row * NNODES + w * 32 + lane];
        unsigned bal = __ballot_sync(0xffffffffu, a > 0.f);
        if (lane == 0) g_mask[row * 16 + w] = bal;
    }
}

// ---------------- tf32 tensor-core GEMM, 128x128 tile, BK=32 ----------------
// Y = A @ W  (bias dropped: it cancels exactly in the following BatchNorm).
// CAT=true: logical A row = [X_row(128) | STE_row(128)], KDIM=256.
// Fused epilogue: per-CTA per-channel sum/sumsq partials -> g_psum/g_psumsq.
template <int KDIM, bool CAT>
__global__ __launch_bounds__(256)
void mma_gemm_kernel(const float* __restrict__ A0, const float* __restrict__ A1,
                     const float* __restrict__ W0, const float* __restrict__ W1,
                     const float* __restrict__ W2,
                     float* __restrict__ Y0, float* __restrict__ Y1,
                     float* __restrict__ Y2, int zbase)
{
    __shared__ unsigned As[128 * 36];
    __shared__ unsigned Bs[32 * 136];
    __shared__ float ssum[2][128], ssq[2][128];

    const int z = blockIdx.z;
    const float* W = (z == 0) ? W0 : (z == 1) ? W1 : W2;
    float*       Y = (z == 0) ? Y0 : (z == 1) ? Y1 : Y2;

    const int tid  = threadIdx.x;
    const int lane = tid & 31;
    const int wid  = tid >> 5;
    const int wm   = wid >> 2;
    const int wn   = wid & 3;
    const int row0 = blockIdx.x * 128;
    const int g    = lane >> 2;
    const int tg   = lane & 3;

    float acc[4][4][4];
#pragma unroll
    for (int mt = 0; mt < 4; mt++)
#pragma unroll
        for (int nt = 0; nt < 4; nt++)
#pragma unroll
            for (int q = 0; q < 4; q++) acc[mt][nt][q] = 0.f;

    for (int k0 = 0; k0 < KDIM; k0 += 32) {
        const float* Abase;
        int kofs;
        if (CAT) {
            if (k0 < 128) { Abase = A0; kofs = k0; }
            else          { Abase = A1; kofs = k0 - 128; }
        } else { Abase = A0; kofs = k0; }

#pragma unroll
        for (int t = 0; t < 4; t++) {
            int i  = tid + 256 * t;
            int r  = i >> 3;
            int kq = (i & 7) << 2;
            float4 v = *(const float4*)(Abase + (size_t)(row0 + r) * 128 + kofs + kq);
            unsigned* d = &As[r * 36 + kq];
            d[0] = f2tf32(v.x); d[1] = f2tf32(v.y);
            d[2] = f2tf32(v.z); d[3] = f2tf32(v.w);
        }
#pragma unroll
        for (int t = 0; t < 4; t++) {
            int i  = tid + 256 * t;
            int k  = i >> 5;
            int n4 = (i & 31) << 2;
            float4 v = *(const float4*)(W + (size_t)(k0 + k) * 128 + n4);
            unsigned* d = &Bs[k * 136 + n4];
            d[0] = f2tf32(v.x); d[1] = f2tf32(v.y);
            d[2] = f2tf32(v.z); d[3] = f2tf32(v.w);
        }
        __syncthreads();

#pragma unroll
        for (int ks = 0; ks < 4; ks++) {
            const int kb = ks * 8;
            unsigned af[4][4];
#pragma unroll
            for (int mt = 0; mt < 4; mt++) {
                int r = wm * 64 + mt * 16 + g;
                af[mt][0] = As[r * 36 + kb + tg];
                af[mt][1] = As[(r + 8) * 36 + kb + tg];
                af[mt][2] = As[r * 36 + kb + tg + 4];
                af[mt][3] = As[(r + 8) * 36 + kb + tg + 4];
            }
            unsigned bf[4][2];
#pragma unroll
            for (int nt = 0; nt < 4; nt++) {
                int c = wn * 32 + nt * 8 + g;
                bf[nt][0] = Bs[(kb + tg) * 136 + c];
                bf[nt][1] = Bs[(kb + tg + 4) * 136 + c];
            }
#pragma unroll
            for (int mt = 0; mt < 4; mt++)
#pragma unroll
                for (int nt = 0; nt < 4; nt++)
                    mma_tf32(acc[mt][nt], af[mt], bf[nt]);
        }
        __syncthreads();
    }

#pragma unroll
    for (int nt = 0; nt < 4; nt++) {
        float se = 0.f, so = 0.f, qe = 0.f, qo = 0.f;
#pragma unroll
        for (int mt = 0; mt < 4; mt++) {
            float c0 = acc[mt][nt][0], c1 = acc[mt][nt][1];
            float c2 = acc[mt][nt][2], c3 = acc[mt][nt][3];
            int r   = row0 + wm * 64 + mt * 16 + g;
            int col = wn * 32 + nt * 8 + tg * 2;
            *(float2*)(Y + (size_t)r * 128 + col)       = make_float2(c0, c1);
            *(float2*)(Y + (size_t)(r + 8) * 128 + col) = make_float2(c2, c3);
            se += c0 + c2;  so += c1 + c3;
            qe += c0 * c0 + c2 * c2;  qo += c1 * c1 + c3 * c3;
        }
#pragma unroll
        for (int o = 4; o < 32; o <<= 1) {
            se += __shfl_xor_sync(0xffffffffu, se, o);
            so += __shfl_xor_sync(0xffffffffu, so, o);
            qe += __shfl_xor_sync(0xffffffffu, qe, o);
            qo += __shfl_xor_sync(0xffffffffu, qo, o);
        }
        if (lane < 4) {
            int col = wn * 32 + nt * 8 + lane * 2;
            ssum[wm][col]     = se;  ssum[wm][col + 1] = so;
            ssq[wm][col]      = qe;  ssq[wm][col + 1]  = qo;
        }
    }
    __syncthreads();
    if (tid < 128) {
        int slot = ((zbase + z) * MBLK + blockIdx.x) * DCH + tid;
        g_psum[slot]   = ssum[0][tid] + ssum[1][tid];
        g_psumsq[slot] = ssq[0][tid] + ssq[1][tid];
    }
}

// ---------------- BN finalize: reduce 384 partials (parallel) ---------------
__global__ void bn_finalize_kernel(const float* __restrict__ g0, const float* __restrict__ be0,
                                   const float* __restrict__ g1, const float* __restrict__ be1,
                                   const float* __restrict__ g2, const float* __restrict__ be2,
                                   int zbase)
{
    __shared__ float ss[512], sq[512];
    int z = blockIdx.x;
    const float* g  = (z == 0) ? g0 : (z == 1) ? g1 : g2;
    const float* be = (z == 0) ? be0 : (z == 1) ? be1 : be2;
    int ch = threadIdx.x & 127, part = threadIdx.x >> 7;
    float s = 0.f, s2 = 0.f;
    for (int b = part; b < MBLK; b += 4) {
        int slot = ((zbase + z) * MBLK + b) * DCH + ch;
        s  += g_psum[slot];
        s2 += g_psumsq[slot];
    }
    ss[threadIdx.x] = s;  sq[threadIdx.x] = s2;
    __syncthreads();
    if (threadIdx.x < 128) {
        s  = ss[ch] + ss[ch + 128] + ss[ch + 256] + ss[ch + 384];
        s2 = sq[ch] + sq[ch + 128] + sq[ch + 256] + sq[ch + 384];
        const float inv_cnt = 1.f / (float)ROWS;
        float mu  = s * inv_cnt;
        float var = s2 * inv_cnt - mu * mu;
        float sc  = g[ch] * rsqrtf(var + 1e-5f);
        g_scale[(zbase + z) * 128 + ch] = sc;
        g_shift[(zbase + z) * 128 + ch] = be[ch] - mu * sc;
    }
}

// ---------------- dense tensor-core masked flash-attention -------------------
// One CTA per (bt, head); 256 threads = 8 warps, warp owns 16 query rows of a
// 128-row q-tile (4 q-tiles). S = Q K^T via tf32 mma, bitmap mask -> -1e30
// (exp underflows to exact 0, matching the NEG fill), online softmax in the
// accumulator layout, P -> per-warp smem buffer -> A-frags, O += P V via mma.
// q,k >= 0 (post BN+ReLU) so all unmasked scores >= 0 -> running max init 0.
__global__ __launch_bounds__(256)
void attn_mma_kernel()
{
    extern __shared__ unsigned smu[];
    unsigned* Kt   = smu;                         // [32][KTPAD] K^T as tf32
    unsigned* Vs   = Kt  + 32 * KTPAD;            // [512][VSPAD] V as tf32
    unsigned* Asq  = Vs  + NNODES * VSPAD;        // [128][AQPAD] Q tile tf32
    unsigned* Pw   = Asq + 128 * AQPAD;           // [8][16][PWPAD] per-warp P
    unsigned* smk  = Pw  + 8 * 16 * PWPAD;        // [512][16] mask bitmap

    const int bt   = blockIdx.x;
    const int h    = blockIdx.y;
    const int tid  = threadIdx.x;
    const int lane = tid & 31;
    const int wid  = tid >> 5;
    const int g    = lane >> 2;
    const int tg   = lane & 3;
    const size_t rowbase = (size_t)bt * NNODES;
    const int cb = h * 32;

    // staging BN params: staged channel == lane
    const float scq = g_scale[0 * 128 + cb + lane], shq = g_shift[0 * 128 + cb + lane];
    const float sck = g_scale[1 * 128 + cb + lane], shk = g_shift[1 * 128 + cb + lane];
    const float scv = g_scale[2 * 128 + cb + lane], shv = g_shift[2 * 128 + cb + lane];

    // stage K^T and V (BN+ReLU fused, tf32)
    for (int idx = tid; idx < NNODES * 32; idx += 256) {
        int n = idx >> 5;                         // (idx & 31) == lane
        float kv = g_kraw[(rowbase + n) * 128 + cb + lane];
        Kt[lane * KTPAD + n] = f2tf32(fmaxf(0.f, fmaf(kv, sck, shk)));
        float vv = g_vraw[(rowbase + n) * 128 + cb + lane];
        Vs[n * VSPAD + lane] = f2tf32(fmaxf(0.f, fmaf(vv, scv, shv)));
    }
    for (int idx = tid; idx < NNODES * 16; idx += 256) smk[idx] = g_mask[idx];
    __syncthreads();

    unsigned* mypw = Pw + wid * 16 * PWPAD;
    const int q0 = wid * 16;

    for (int qt = 0; qt < 4; qt++) {
        // stage this q-tile (BN+ReLU, tf32)
        for (int idx = tid; idx < 128 * 32; idx += 256) {
            int r = idx >> 5;
            float qv = g_qraw[(rowbase + qt * 128 + r) * 128 + cb + lane];
            Asq[r * AQPAD + lane] = f2tf32(fmaxf(0.f, fmaf(qv, scq, shq)));
        }
        __syncthreads();

        const int r0 = qt * 128 + q0 + g;     // query node of lane's low rows
        const int r1 = r0 + 8;

        float m0 = 0.f, m1 = 0.f, l0 = 0.f, l1 = 0.f;
        float o[4][4];
#pragma unroll
        for (int nt = 0; nt < 4; nt++)
#pragma unroll
            for (int q = 0; q < 4; q++) o[nt][q] = 0.f;

        for (int kv = 0; kv < 8; kv++) {
            const int n0 = kv * 64;

            // ---- S = Q K^T for 16x64 strip ----
            float c[8][4];
#pragma unroll
            for (int nt = 0; nt < 8; nt++) {
                c[nt][0] = 0.f; c[nt][1] = 0.f; c[nt][2] = 0.f; c[nt][3] = 0.f;
            }
#pragma unroll
            for (int ks = 0; ks < 4; ks++) {
                const int kb = ks * 8;
                unsigned a[4];
                a[0] = Asq[(q0 + g) * AQPAD + kb + tg];
                a[1] = Asq[(q0 + g + 8) * AQPAD + kb + tg];
                a[2] = Asq[(q0 + g) * AQPAD + kb + tg + 4];
                a[3] = Asq[(q0 + g + 8) * AQPAD + kb + tg + 4];
#pragma unroll
                for (int nt = 0; nt < 8; nt++) {
                    int cc = n0 + nt * 8 + g;
                    unsigned b[2];
                    b[0] = Kt[(kb + tg) * KTPAD + cc];
                    b[1] = Kt[(kb + tg + 4) * KTPAD + cc];
                    mma_tf32(c[nt], a, b);
                }
            }

            // ---- mask + scale; tile max ----
            unsigned w0a = smk[r0 * 16 + kv * 2], w0b = smk[r0 * 16 + kv * 2 + 1];
            unsigned w1a = smk[r1 * 16 + kv * 2], w1b = smk[r1 * 16 + kv * 2 + 1];
            float tm0 = 0.f, tm1 = 0.f;
#pragma unroll
            for (int nt = 0; nt < 8; nt++) {
                unsigned mw0 = (nt < 4) ? w0a : w0b;
                unsigned mw1 = (nt < 4) ? w1a : w1b;
                int sh = (nt & 3) * 8 + 2 * tg;
                float s;
                s = ((mw0 >> sh) & 1u)       ? c[nt][0] * 0.5f : -1e30f;
                c[nt][0] = s; tm0 = fmaxf(tm0, s);
                s = ((mw0 >> (sh + 1)) & 1u) ? c[nt][1] * 0.5f : -1e30f;
                c[nt][1] = s; tm0 = fmaxf(tm0, s);
                s = ((mw1 >> sh) & 1u)       ? c[nt][2] * 0.5f : -1e30f;
                c[nt][2] = s; tm1 = fmaxf(tm1, s);
                s = ((mw1 >> (sh + 1)) & 1u) ? c[nt][3] * 0.5f : -1e30f;
                c[nt][3] = s; tm1 = fmaxf(tm1, s);
            }
            tm0 = fmaxf(tm0, __shfl_xor_sync(0xffffffffu, tm0, 1));
            tm0 = fmaxf(tm0, __shfl_xor_sync(0xffffffffu, tm0, 2));
            tm1 = fmaxf(tm1, __shfl_xor_sync(0xffffffffu, tm1, 1));
            tm1 = fmaxf(tm1, __shfl_xor_sync(0xffffffffu, tm1, 2));

            float nm0 = fmaxf(m0, tm0), nm1 = fmaxf(m1, tm1);
            float corr0 = __expf(m0 - nm0), corr1 = __expf(m1 - nm1);
            m0 = nm0; m1 = nm1;

            // ---- exp, row sums, stash P (tf32) ----
            float ts0 = 0.f, ts1 = 0.f;
#pragma unroll
            for (int nt = 0; nt < 8; nt++) {
                float p00 = __expf(c[nt][0] - nm0), p01 = __expf(c[nt][1] - nm0);
                float p10 = __expf(c[nt][2] - nm1), p11 = __expf(c[nt][3] - nm1);
                ts0 += p00 + p01;  ts1 += p10 + p11;
                uint2 u0 = make_uint2(f2tf32(p00), f2tf32(p01));
                uint2 u1 = make_uint2(f2tf32(p10), f2tf32(p11));
                *(uint2*)&mypw[g * PWPAD + nt * 8 + 2 * tg]       = u0;
                *(uint2*)&mypw[(g + 8) * PWPAD + nt * 8 + 2 * tg] = u1;
            }
            ts0 += __shfl_xor_sync(0xffffffffu, ts0, 1);
            ts0 += __shfl_xor_sync(0xffffffffu, ts0, 2);
            ts1 += __shfl_xor_sync(0xffffffffu, ts1, 1);
            ts1 += __shfl_xor_sync(0xffffffffu, ts1, 2);
            l0 = l0 * corr0 + ts0;
            l1 = l1 * corr1 + ts1;
#pragma unroll
            for (int nt = 0; nt < 4; nt++) {
                o[nt][0] *= corr0; o[nt][1] *= corr0;
                o[nt][2] *= corr1; o[nt][3] *= corr1;
            }
            __syncwarp();

            // ---- O += P V for this kv tile ----
#pragma unroll
            for (int ks = 0; ks < 8; ks++) {
                const int kb = ks * 8;
                unsigned a[4];
                a[0] = mypw[g * PWPAD + kb + tg];
                a[1] = mypw[(g + 8) * PWPAD + kb + tg];
                a[2] = mypw[g * PWPAD + kb + tg + 4];
                a[3] = mypw[(g + 8) * PWPAD + kb + tg + 4];
#pragma unroll
                for (int nt = 0; nt < 4; nt++) {
                    unsigned b[2];
                    b[0] = Vs[(n0 + kb + tg) * VSPAD + nt * 8 + g];
                    b[1] = Vs[(n0 + kb + tg + 4) * VSPAD + nt * 8 + g];
                    mma_tf32(o[nt], a, b);
                }
            }
            __syncwarp();   // before next kv overwrites mypw
        }

        // ---- epilogue: normalize and write ----
        float il0 = 1.f / l0, il1 = 1.f / l1;
#pragma unroll
        for (int nt = 0; nt < 4; nt++) {
            int col = cb + nt * 8 + 2 * tg;
            *(float2*)&g_aout[(rowbase + r0) * 128 + col] =
                make_float2(o[nt][0] * il0, o[nt][1] * il0);
            *(float2*)&g_aout[(rowbase + r1) * 128 + col] =
                make_float2(o[nt][2] * il1, o[nt][3] * il1);
        }
        __syncthreads();   // before re-staging Asq
    }
}

// ---------------- final BN+ReLU into d_out -----------------------------------
__global__ void bn_apply_kernel(float* __restrict__ out)
{
    size_t i = (size_t)blockIdx.x * blockDim.x + threadIdx.x;
    if (i >= (size_t)ROWS * DCH) return;
    int ch = (int)(i & 127);
    out[i] = fmaxf(0.f, fmaf(g_oraw[i], g_scale[3 * 128 + ch], g_shift[3 * 128 + ch]));
}

// =============================================================================
extern "C" void kernel_launch(void* const* d_in, const int* in_sizes, int n_in,
                              void* d_out, int out_size)
{
    (void)in_sizes; (void)n_in; (void)out_size;
    const float* X     = (const float*)d_in[0];
    const float* STE   = (const float*)d_in[1];
    const float* A     = (const float*)d_in[2];
    const float* Wq    = (const float*)d_in[3];
    const float* gq    = (const float*)d_in[5];
    const float* betaq = (const float*)d_in[6];
    const float* Wk    = (const float*)d_in[7];
    const float* gk    = (const float*)d_in[9];
    const float* betak = (const float*)d_in[10];
    const float* Wv    = (const float*)d_in[11];
    const float* gv    = (const float*)d_in[13];
    const float* betav = (const float*)d_in[14];
    const float* Wo    = (const float*)d_in[15];
    const float* go    = (const float*)d_in[17];
    const float* betao = (const float*)d_in[18];
    float* out = (float*)d_out;

    void *pq, *pk, *pv, *pa, *po;
    cudaGetSymbolAddress(&pq, g_qraw);
    cudaGetSymbolAddress(&pk, g_kraw);
    cudaGetSymbolAddress(&pv, g_vraw);
    cudaGetSymbolAddress(&pa, g_aout);
    cudaGetSymbolAddress(&po, g_oraw);

    const int smem_attn = (32 * KTPAD + NNODES * VSPAD + 128 * AQPAD +
                           8 * 16 * PWPAD + NNODES * 16) * (int)sizeof(unsigned);
    cudaFuncSetAttribute(attn_mma_kernel, cudaFuncAttributeMaxDynamicSharedMemorySize,
                         smem_attn);

    // 1) adjacency -> bitmap
    build_mask_kernel<<<16, 1024>>>(A);

    // 2) q/k/v projections (tf32 tensor cores, fused BN partial stats)
    mma_gemm_kernel<256, true><<<dim3(MBLK, 1, 3), 256>>>(
        X, STE, Wq, Wk, Wv, (float*)pq, (float*)pk, (float*)pv, 0);

    // 3) BN finalize for q/k/v (parallel)
    bn_finalize_kernel<<<3, 512>>>(gq, betaq, gk, betak, gv, betav, 0);

    // 4) dense tensor-core masked flash-attention (BN+ReLU fused into staging)
    attn_mma_kernel<<<dim3(NBT, NH), 256, smem_attn>>>();

    // 5) output projection (fused BN partial stats)
    mma_gemm_kernel<128, false><<<dim3(MBLK, 1, 1), 256>>>(
        (float*)pa, nullptr, Wo, Wo, Wo, (float*)po, (float*)po, (float*)po, 3);

    // 6) BN finalize for output
    bn_finalize_kernel<<<1, 512>>>(go, betao, go, betao, go, betao, 3);

    // 7) BN + ReLU -> d_out
    bn_apply_kernel<<<(ROWS * DCH + 255) / 256, 256>>>(out);
}